// round 4
// baseline (speedup 1.0000x reference)
#include <cuda_runtime.h>
#include <cstdint>
#include <cstddef>

// ---------------------------------------------------------------------------
// Shapes: B=256,S=128 -> M=32768 tokens, H=768, A=512, N=10, C=3, K=3
// ---------------------------------------------------------------------------
#define HDIM  768
#define ADIM  512
#define NTASK 10
#define CCAP  3
#define KCAP  3
#define BSTOK 32768

// ---------------------------------------------------------------------------
// Scratch (device globals; allocation forbidden)
// ---------------------------------------------------------------------------
__device__ float g_w30[HDIM * 32];                        // sem weights, (H,32) col j=c*10+n
__device__ float g_semb[32];                              // sem bias per col
__device__ float g_vote[(size_t)KCAP * BSTOK * CCAP];     // (K,BS,C) flat
__device__ float g_w9[10 * ADIM];                         // rank-9 fc1 correction (+row9=bias)
__device__ float g_gate1[ADIM];                           // sigmoid(s*efc1[t])
__device__ float g_gate2[HDIM];                           // sigmoid(s*efc2[t])
__device__ float g_a1[(size_t)BSTOK * ADIM];              // fc1 activations

// ---------------------------------------------------------------------------
// Helpers
// ---------------------------------------------------------------------------
__device__ __forceinline__ uint32_t sptr(const void* p) {
    return static_cast<uint32_t>(__cvta_generic_to_shared(p));
}

__device__ __forceinline__ void mma_tf32(float* c, const uint32_t* a, const uint32_t* b) {
    asm volatile(
        "mma.sync.aligned.m16n8k8.row.col.f32.tf32.tf32.f32 "
        "{%0,%1,%2,%3}, {%4,%5,%6,%7}, {%8,%9}, {%0,%1,%2,%3};"
        : "+f"(c[0]), "+f"(c[1]), "+f"(c[2]), "+f"(c[3])
        : "r"(a[0]), "r"(a[1]), "r"(a[2]), "r"(a[3]), "r"(b[0]), "r"(b[1]));
}

#define CP16(dst, src) \
    asm volatile("cp.async.cg.shared.global [%0], [%1], 16;" :: "r"(sptr(dst)), "l"(src))
#define CP_COMMIT() asm volatile("cp.async.commit_group;")
#define CP_WAIT1()  asm volatile("cp.async.wait_group 1;")
#define CP_WAIT0()  asm volatile("cp.async.wait_group 0;")

__device__ __forceinline__ float gelu_exact(float v) {
    return 0.5f * v * (1.0f + erff(v * 0.70710678118654752f));
}
__device__ __forceinline__ float sigmoidf_(float z) {
    return 1.0f / (1.0f + expf(-z));
}
__device__ __forceinline__ int read_t(const int* p) {
    int v = *p;
    if (v < 0 || v >= NTASK) v = (int)__int_as_float(v);
    return v;
}
__device__ __forceinline__ float read_s(const int* p) {
    int v = *p;
    if (v >= 0 && v <= 1000000) return (float)v;
    return __int_as_float(v);
}

// ---------------------------------------------------------------------------
// Prep A: reorder sem weights (N,H,C)->(H,32) with j=c*10+n, and sem bias.
// ---------------------------------------------------------------------------
__global__ void prep_kernel(const float* __restrict__ sem_w, const float* __restrict__ sem_b) {
    int idx = blockIdx.x * blockDim.x + threadIdx.x;
    if (idx < HDIM * 32) {
        int h = idx / 32, j = idx % 32;
        float v = 0.0f;
        if (j < 30) {
            int n = j % NTASK, c = j / NTASK;
            v = sem_w[(size_t)n * HDIM * CCAP + (size_t)h * CCAP + c];
        }
        g_w30[idx] = v;
    } else if (idx < HDIM * 32 + 32) {
        int j = idx - HDIM * 32;
        float v = 0.0f;
        if (j < 30) {
            int n = j % NTASK, c = j / NTASK;
            v = sem_b[n * CCAP + c];
        }
        g_semb[j] = v;
    }
}

// ---------------------------------------------------------------------------
// Prep B: rank-9 fc1 correction  W9[j][n] = sum_k gl[k]*LW[j][k]*W1[k][n],
// row 9 = sum_k gl[k]*lb[k]*W1[k][n] + fc1_b[n]; plus both gate vectors.
// ---------------------------------------------------------------------------
__global__ void w9_kernel(const float* __restrict__ larger_w, const float* __restrict__ larger_b,
                          const float* __restrict__ elarger, const float* __restrict__ fc1_w,
                          const float* __restrict__ fc1_b, const float* __restrict__ efc1,
                          const float* __restrict__ efc2, const int* __restrict__ tp,
                          const int* __restrict__ sp) {
    int n = blockIdx.x * 256 + threadIdx.x;
    if (n >= HDIM) return;
    const int t = read_t(tp);
    const float sf = read_s(sp);

    g_gate2[n] = sigmoidf_(sf * efc2[(size_t)t * HDIM + n]);
    if (n >= ADIM) return;
    g_gate1[n] = sigmoidf_(sf * efc1[(size_t)t * ADIM + n]);

    float acc[10];
#pragma unroll
    for (int j = 0; j < 10; j++) acc[j] = 0.0f;
    for (int k = 0; k < HDIM; k++) {
        float gl = sigmoidf_(sf * elarger[(size_t)t * HDIM + k]);
        float gw = gl * fc1_w[(size_t)k * ADIM + n];
#pragma unroll
        for (int j = 0; j < 9; j++) acc[j] += gw * larger_w[j * HDIM + k];
        acc[9] += gw * larger_b[k];
    }
#pragma unroll
    for (int j = 0; j < 9; j++) g_w9[j * ADIM + n] = acc[j];
    g_w9[9 * ADIM + n] = acc[9] + fc1_b[n];
}

// ---------------------------------------------------------------------------
// Fused sem GEMM (x @ W30, 128x32 tile, K=768, cp.async 2-stage) + capsule
// dynamic routing in the epilogue. Writes g_vote in (K,BS,C) layout.
// All-static smem (47,104 B).
// ---------------------------------------------------------------------------
__global__ __launch_bounds__(256) void semroute_kernel(const float* __restrict__ x,
                                                       const float* __restrict__ w30,
                                                       const float* __restrict__ route_w,
                                                       const int* __restrict__ tp, int M) {
    constexpr int BM = 128, BK = 32, AST = BK + 4, BST = 40;
    __shared__ float As[2 * BM * AST];
    __shared__ float Bs[2 * BK * BST];

    const int tid = threadIdx.x;
    const int wid = tid >> 5, lane = tid & 31;
    const int gr = lane >> 2, gc = lane & 3;
    const int wm = wid * 16;            // 8 warps x 16 rows
    const int m0 = blockIdx.x * BM;

    float acc[4][4];
#pragma unroll
    for (int j = 0; j < 4; j++)
#pragma unroll
        for (int q = 0; q < 4; q++) acc[j][q] = 0.0f;

    const int NC = HDIM / BK;  // 24

    {
        const float* ab = x + (size_t)m0 * HDIM;
#pragma unroll
        for (int it = 0; it < 4; it++) {
            int idx = tid + it * 256;
            int r = idx >> 3, c4 = (idx & 7) << 2;
            CP16(As + r * AST + c4, ab + (size_t)r * HDIM + c4);
        }
        int r = tid >> 3, c4 = (tid & 7) << 2;
        CP16(Bs + r * BST + c4, w30 + r * 32 + c4);
        CP_COMMIT();
    }

    for (int kc = 0; kc < NC; kc++) {
        int st = kc & 1;
        if (kc + 1 < NC) {
            const float* ab = x + (size_t)m0 * HDIM + (kc + 1) * BK;
            float* ad = As + (st ^ 1) * BM * AST;
#pragma unroll
            for (int it = 0; it < 4; it++) {
                int idx = tid + it * 256;
                int r = idx >> 3, c4 = (idx & 7) << 2;
                CP16(ad + r * AST + c4, ab + (size_t)r * HDIM + c4);
            }
            float* bd = Bs + (st ^ 1) * BK * BST;
            int r = tid >> 3, c4 = (tid & 7) << 2;
            CP16(bd + r * BST + c4, w30 + (size_t)(kc + 1) * BK * 32 + r * 32 + c4);
            CP_COMMIT();
            CP_WAIT1();
        } else {
            CP_WAIT0();
        }
        __syncthreads();

        const float* Al = As + st * BM * AST;
        const float* Bl = Bs + st * BK * BST;
#pragma unroll
        for (int kk = 0; kk < BK; kk += 8) {
            uint32_t a_[4], b_[4][2];
            int row = wm + gr;
            a_[0] = __float_as_uint(Al[row * AST + kk + gc]);
            a_[1] = __float_as_uint(Al[(row + 8) * AST + kk + gc]);
            a_[2] = __float_as_uint(Al[row * AST + kk + gc + 4]);
            a_[3] = __float_as_uint(Al[(row + 8) * AST + kk + gc + 4]);
#pragma unroll
            for (int j = 0; j < 4; j++) {
                int col = j * 8 + gr;
                b_[j][0] = __float_as_uint(Bl[(kk + gc) * BST + col]);
                b_[j][1] = __float_as_uint(Bl[(kk + gc + 4) * BST + col]);
            }
#pragma unroll
            for (int j = 0; j < 4; j++) mma_tf32(acc[j], a_, b_[j]);
        }
        __syncthreads();
    }

    float* sem_s = As;  // reuse: 128 rows, stride 33
    float* rw = Bs;     // reuse: 270 floats
#pragma unroll
    for (int j = 0; j < 4; j++)
#pragma unroll
        for (int q = 0; q < 4; q++) {
            int row = wm + gr + ((q >= 2) ? 8 : 0);
            int col = j * 8 + gc * 2 + (q & 1);
            sem_s[row * 33 + col] = acc[j][q] + __ldg(&g_semb[col]);
        }
    for (int i = tid; i < KCAP * NTASK * CCAP * CCAP; i += 256) rw[i] = route_w[i];
    __syncthreads();

    if (tid < BM) {
        const int m = m0 + tid;
        const int tval = read_t(tp);

        float uf[30];
#pragma unroll
        for (int i = 0; i < 30; i++) uf[i] = sem_s[tid * 33 + i];
#pragma unroll
        for (int c = 0; c < CCAP; c++) {
            float sn = 1e-16f;
#pragma unroll
            for (int n = 0; n < NTASK; n++) {
                float v = uf[c * NTASK + n];
                sn += v * v;
            }
            float sc = sqrtf(sn) / (1.0f + sn);
#pragma unroll
            for (int n = 0; n < NTASK; n++) uf[c * NTASK + n] *= sc;
        }

        for (int k = 0; k < KCAP; k++) {
            float pr[NTASK][CCAP];
#pragma unroll
            for (int n = 0; n < NTASK; n++)
#pragma unroll
                for (int d = 0; d < CCAP; d++) {
                    float s = 0.0f;
#pragma unroll
                    for (int c = 0; c < CCAP; c++)
                        s += uf[n * CCAP + c] * rw[((k * NTASK + n) * CCAP + c) * CCAP + d];
                    pr[n][d] = s;
                }

            float lg[NTASK];
#pragma unroll
            for (int n = 0; n < NTASK; n++) lg[n] = 0.0f;
            float vote[CCAP] = {0.0f, 0.0f, 0.0f};

#pragma unroll
            for (int it = 0; it < 3; it++) {
                float ml[NTASK], mx = -1e30f;
#pragma unroll
                for (int n = 0; n < NTASK; n++) {
                    ml[n] = (n <= tval) ? lg[n] : -10000.0f;
                    mx = fmaxf(mx, ml[n]);
                }
                float p[NTASK], sum = 0.0f;
#pragma unroll
                for (int n = 0; n < NTASK; n++) {
                    p[n] = expf(ml[n] - mx);
                    sum += p[n];
                }
                float inv = 1.0f / sum;
#pragma unroll
                for (int c = 0; c < CCAP; c++) {
                    float s = 0.0f;
#pragma unroll
                    for (int n = 0; n < NTASK; n++) s += p[n] * pr[n][c];
                    vote[c] = s * inv;
                }
                if (it < 2) {
                    float sn = 1e-16f;
#pragma unroll
                    for (int c = 0; c < CCAP; c++) sn += vote[c] * vote[c];
                    float sc = sqrtf(sn) / (1.0f + sn);
#pragma unroll
                    for (int n = 0; n < NTASK; n++) {
                        float s = 0.0f;
#pragma unroll
                        for (int c = 0; c < CCAP; c++) s += pr[n][c] * vote[c];
                        lg[n] += s * sc;
                    }
                }
            }
            float* vp = g_vote + ((size_t)k * M + m) * CCAP;
#pragma unroll
            for (int c = 0; c < CCAP; c++) vp[c] = vote[c];
        }
    }
}

// ---------------------------------------------------------------------------
// Big pipelined TF32 GEMM, 128x128x16 tiles, 2-stage cp.async.
// ALL-STATIC smem: As 20480 + Bs 17408 + ex 10240 = 48128 B <= 48KB.
// EPI 1 (fc1): a1 = gelu(x@W1 + h9@W9 + W9row9) * gate1
// EPI 2 (fc2): out = x + gelu(a1@W2 + b2) * gate2
// ---------------------------------------------------------------------------
template <int EPI>
__global__ __launch_bounds__(256) void gemm_big(const float* __restrict__ A,
                                                const float* __restrict__ Bm,
                                                float* __restrict__ C, int M, int N, int K,
                                                const float* __restrict__ bias,
                                                const float* __restrict__ gate,
                                                const float* __restrict__ xres,
                                                const float* __restrict__ w9,
                                                const float* __restrict__ h9g) {
    constexpr int BM = 128, BN = 128, BK = 16;
    constexpr int AST = BK + 4, BST = BN + 8;
    __shared__ float As[2 * BM * AST];   // 20480 B
    __shared__ float Bs[2 * BK * BST];   // 17408 B
    __shared__ float ex[2560];           // 10240 B

    const int tid = threadIdx.x;
    const int wid = tid >> 5, lane = tid & 31;
    const int gr = lane >> 2, gc = lane & 3;
    const int wm = (wid >> 2) * 64;       // 2 warp-rows
    const int wn = (wid & 3) * 32;        // 4 warp-cols
    const int m0 = blockIdx.y * BM, n0 = blockIdx.x * BN;

    // ---- small epilogue operand staging (covered by mainloop syncs)
    if (EPI == 1) {
        float* h9s = ex;                  // 1152 floats
        float* w9s = ex + 1152;           // 1280 floats
        float* gs = ex + 2432;            // 128 floats
        const float4* hsrc = (const float4*)(h9g + (size_t)m0 * 9);
        for (int i = tid; i < 288; i += 256) ((float4*)h9s)[i] = hsrc[i];
        for (int i = tid; i < 320; i += 256) {
            int j = i >> 5, c = i & 31;
            ((float4*)w9s)[j * 32 + c] = *(const float4*)(w9 + j * ADIM + n0 + c * 4);
        }
        if (tid < 32) ((float4*)gs)[tid] = *(const float4*)(gate + n0 + tid * 4);
    } else {
        float* biass = ex;                // 128 floats
        float* gs = ex + 128;             // 128 floats
        if (tid < 32)
            ((float4*)biass)[tid] = *(const float4*)(bias + n0 + tid * 4);
        else if (tid < 64)
            ((float4*)gs)[tid - 32] = *(const float4*)(gate + n0 + (tid - 32) * 4);
    }

    float acc[4][4][4];
#pragma unroll
    for (int i = 0; i < 4; i++)
#pragma unroll
        for (int j = 0; j < 4; j++)
#pragma unroll
            for (int q = 0; q < 4; q++) acc[i][j][q] = 0.0f;

    const int NC = K / BK;

    // prefetch chunk 0: A 128x16 = 512 float4, B 16x128 = 512 float4
    {
        const float* ab = A + (size_t)m0 * K;
#pragma unroll
        for (int it = 0; it < 2; it++) {
            int idx = tid + it * 256;
            int r = idx >> 2, c4 = (idx & 3) << 2;
            CP16(As + r * AST + c4, ab + (size_t)r * K + c4);
        }
        const float* bb = Bm + n0;
#pragma unroll
        for (int it = 0; it < 2; it++) {
            int idx = tid + it * 256;
            int r = idx >> 5, c4 = (idx & 31) << 2;
            CP16(Bs + r * BST + c4, bb + (size_t)r * N + c4);
        }
        CP_COMMIT();
    }

    for (int kc = 0; kc < NC; kc++) {
        int st = kc & 1;
        if (kc + 1 < NC) {
            const float* ab = A + (size_t)m0 * K + (kc + 1) * BK;
            float* ad = As + (st ^ 1) * BM * AST;
#pragma unroll
            for (int it = 0; it < 2; it++) {
                int idx = tid + it * 256;
                int r = idx >> 2, c4 = (idx & 3) << 2;
                CP16(ad + r * AST + c4, ab + (size_t)r * K + c4);
            }
            const float* bb = Bm + (size_t)(kc + 1) * BK * N + n0;
            float* bd = Bs + (st ^ 1) * BK * BST;
#pragma unroll
            for (int it = 0; it < 2; it++) {
                int idx = tid + it * 256;
                int r = idx >> 5, c4 = (idx & 31) << 2;
                CP16(bd + r * BST + c4, bb + (size_t)r * N + c4);
            }
            CP_COMMIT();
            CP_WAIT1();
        } else {
            CP_WAIT0();
        }
        __syncthreads();

        const float* Al = As + st * BM * AST;
        const float* Bl = Bs + st * BK * BST;
#pragma unroll
        for (int kk = 0; kk < BK; kk += 8) {
            uint32_t a_[4][4], b_[4][2];
#pragma unroll
            for (int i = 0; i < 4; i++) {
                int row = wm + i * 16 + gr;
                a_[i][0] = __float_as_uint(Al[row * AST + kk + gc]);
                a_[i][1] = __float_as_uint(Al[(row + 8) * AST + kk + gc]);
                a_[i][2] = __float_as_uint(Al[row * AST + kk + gc + 4]);
                a_[i][3] = __float_as_uint(Al[(row + 8) * AST + kk + gc + 4]);
            }
#pragma unroll
            for (int j = 0; j < 4; j++) {
                int col = wn + j * 8 + gr;
                b_[j][0] = __float_as_uint(Bl[(kk + gc) * BST + col]);
                b_[j][1] = __float_as_uint(Bl[(kk + gc + 4) * BST + col]);
            }
#pragma unroll
            for (int i = 0; i < 4; i++)
#pragma unroll
                for (int j = 0; j < 4; j++) mma_tf32(acc[i][j], a_[i], b_[j]);
        }
        __syncthreads();
    }

    // ---- epilogue (float2 coalesced stores)
    const float* h9s = ex;
    const float* w9s = ex + 1152;
    const float* gsE = (EPI == 1) ? (ex + 2432) : (ex + 128);
    const float* biass = ex;

#pragma unroll
    for (int i = 0; i < 4; i++) {
#pragma unroll
        for (int j = 0; j < 4; j++) {
            int rB0 = wm + i * 16 + gr;
            int cB = wn + j * 8 + gc * 2;
            int cG = n0 + cB;
#pragma unroll
            for (int h = 0; h < 2; h++) {
                int rB = rB0 + h * 8;
                int rG = m0 + rB;
                float v0 = acc[i][j][h * 2 + 0];
                float v1 = acc[i][j][h * 2 + 1];
                if (EPI == 1) {
                    float c0 = w9s[9 * BN + cB], c1 = w9s[9 * BN + cB + 1];
                    const float* hr = h9s + rB * 9;
#pragma unroll
                    for (int jj = 0; jj < 9; jj++) {
                        float hv = hr[jj];
                        c0 += hv * w9s[jj * BN + cB];
                        c1 += hv * w9s[jj * BN + cB + 1];
                    }
                    v0 = gelu_exact(v0 + c0) * gsE[cB];
                    v1 = gelu_exact(v1 + c1) * gsE[cB + 1];
                } else {
                    v0 = gelu_exact(v0 + biass[cB]) * gsE[cB];
                    v1 = gelu_exact(v1 + biass[cB + 1]) * gsE[cB + 1];
                    float2 xv = *(const float2*)(xres + (size_t)rG * N + cG);
                    v0 += xv.x;
                    v1 += xv.y;
                }
                *(float2*)(C + (size_t)rG * N + cG) = make_float2(v0, v1);
            }
        }
    }
}

// ---------------------------------------------------------------------------
// Launch — kernel launches only; no attribute calls, no dynamic smem.
// ---------------------------------------------------------------------------
extern "C" void kernel_launch(void* const* d_in, const int* in_sizes, int n_in,
                              void* d_out, int out_size) {
    const float* x        = (const float*)d_in[0];
    const int*   tp       = (const int*)d_in[1];
    const int*   sp       = (const int*)d_in[2];
    const float* fc1_w    = (const float*)d_in[3];
    const float* fc1_b    = (const float*)d_in[4];
    const float* fc2_w    = (const float*)d_in[5];
    const float* fc2_b    = (const float*)d_in[6];
    const float* efc1     = (const float*)d_in[7];
    const float* efc2     = (const float*)d_in[8];
    const float* sem_w    = (const float*)d_in[9];
    const float* sem_b    = (const float*)d_in[10];
    const float* route_w  = (const float*)d_in[11];
    const float* larger_w = (const float*)d_in[12];
    const float* larger_b = (const float*)d_in[13];
    const float* elarger  = (const float*)d_in[14];
    float* out = (float*)d_out;

    const int M = in_sizes[0] / HDIM;  // 32768

    float *p_w30, *p_vote, *p_w9, *p_g1, *p_g2, *p_a1;
    cudaGetSymbolAddress((void**)&p_w30, g_w30);
    cudaGetSymbolAddress((void**)&p_vote, g_vote);
    cudaGetSymbolAddress((void**)&p_w9, g_w9);
    cudaGetSymbolAddress((void**)&p_g1, g_gate1);
    cudaGetSymbolAddress((void**)&p_g2, g_gate2);
    cudaGetSymbolAddress((void**)&p_a1, g_a1);

    // 1) weight reorders + rank-9 correction + gates
    prep_kernel<<<(HDIM * 32 + 32 + 255) / 256, 256>>>(sem_w, sem_b);
    w9_kernel<<<3, 256>>>(larger_w, larger_b, elarger, fc1_w, fc1_b, efc1, efc2, tp, sp);

    // 2) sem GEMM + routing fused
    semroute_kernel<<<M / 128, 256>>>(x, p_w30, route_w, tp, M);

    // 3) fc1: a1 = gelu(x@W1 + rank9) * gate1
    gemm_big<1><<<dim3(ADIM / 128, M / 128), 256>>>(
        x, fc1_w, p_a1, M, ADIM, HDIM, nullptr, p_g1, nullptr, p_w9, p_vote);

    // 4) fc2: out = x + gelu(a1@W2 + b2) * gate2
    gemm_big<2><<<dim3(HDIM / 128, M / 128), 256>>>(
        p_a1, fc2_w, out, M, HDIM, ADIM, fc2_b, p_g2, x, nullptr, nullptr);
}

// round 5
// speedup vs baseline: 1.1341x; 1.1341x over previous
#include <cuda_runtime.h>
#include <cstdint>
#include <cstddef>

// ---------------------------------------------------------------------------
// Shapes: B=256,S=128 -> M=32768 tokens, H=768, A=512, N=10, C=3, K=3
// ---------------------------------------------------------------------------
#define HDIM  768
#define ADIM  512
#define NTASK 10
#define CCAP  3
#define KCAP  3
#define BSTOK 32768

// ---------------------------------------------------------------------------
// Scratch (device globals; allocation forbidden)
// ---------------------------------------------------------------------------
__device__ float g_w30[HDIM * 32];                        // sem weights, (H,32) col j=c*10+n
__device__ float g_semb[32];                              // sem bias per col
__device__ float g_vote[(size_t)KCAP * BSTOK * CCAP];     // (K,BS,C) flat
__device__ float g_w9[10 * ADIM];                         // rank-9 fc1 correction (+row9=bias)
__device__ float g_gate1[ADIM];                           // sigmoid(s*efc1[t])
__device__ float g_gate2[HDIM];                           // sigmoid(s*efc2[t])
__device__ float g_a1[(size_t)BSTOK * ADIM];              // fc1 activations

// ---------------------------------------------------------------------------
// Helpers
// ---------------------------------------------------------------------------
__device__ __forceinline__ uint32_t sptr(const void* p) {
    return static_cast<uint32_t>(__cvta_generic_to_shared(p));
}

__device__ __forceinline__ void mma_tf32(float* c, const uint32_t* a, const uint32_t* b) {
    asm volatile(
        "mma.sync.aligned.m16n8k8.row.col.f32.tf32.tf32.f32 "
        "{%0,%1,%2,%3}, {%4,%5,%6,%7}, {%8,%9}, {%0,%1,%2,%3};"
        : "+f"(c[0]), "+f"(c[1]), "+f"(c[2]), "+f"(c[3])
        : "r"(a[0]), "r"(a[1]), "r"(a[2]), "r"(a[3]), "r"(b[0]), "r"(b[1]));
}

#define CP16(dst, src) \
    asm volatile("cp.async.cg.shared.global [%0], [%1], 16;" :: "r"(sptr(dst)), "l"(src))
#define CP_COMMIT() asm volatile("cp.async.commit_group;")
#define CP_WAIT1()  asm volatile("cp.async.wait_group 1;")
#define CP_WAIT0()  asm volatile("cp.async.wait_group 0;")

__device__ __forceinline__ float gelu_exact(float v) {
    return 0.5f * v * (1.0f + erff(v * 0.70710678118654752f));
}
__device__ __forceinline__ float sigmoidf_(float z) {
    return 1.0f / (1.0f + expf(-z));
}
__device__ __forceinline__ int read_t(const int* p) {
    int v = *p;
    if (v < 0 || v >= NTASK) v = (int)__int_as_float(v);
    return v;
}
__device__ __forceinline__ float read_s(const int* p) {
    int v = *p;
    if (v >= 0 && v <= 1000000) return (float)v;
    return __int_as_float(v);
}

// ---------------------------------------------------------------------------
// Prep A: reorder sem weights (N,H,C)->(H,32) with j=c*10+n, and sem bias.
// ---------------------------------------------------------------------------
__global__ void prep_kernel(const float* __restrict__ sem_w, const float* __restrict__ sem_b) {
    int idx = blockIdx.x * blockDim.x + threadIdx.x;
    if (idx < HDIM * 32) {
        int h = idx / 32, j = idx % 32;
        float v = 0.0f;
        if (j < 30) {
            int n = j % NTASK, c = j / NTASK;
            v = sem_w[(size_t)n * HDIM * CCAP + (size_t)h * CCAP + c];
        }
        g_w30[idx] = v;
    } else if (idx < HDIM * 32 + 32) {
        int j = idx - HDIM * 32;
        float v = 0.0f;
        if (j < 30) {
            int n = j % NTASK, c = j / NTASK;
            v = sem_b[n * CCAP + c];
        }
        g_semb[j] = v;
    }
}

// ---------------------------------------------------------------------------
// Prep B: rank-9 fc1 correction  W9[j][n] = sum_k gl[k]*LW[j][k]*W1[k][n],
// row 9 = sum_k gl[k]*lb[k]*W1[k][n] + fc1_b[n]; plus both gate vectors.
// ---------------------------------------------------------------------------
__global__ void w9_kernel(const float* __restrict__ larger_w, const float* __restrict__ larger_b,
                          const float* __restrict__ elarger, const float* __restrict__ fc1_w,
                          const float* __restrict__ fc1_b, const float* __restrict__ efc1,
                          const float* __restrict__ efc2, const int* __restrict__ tp,
                          const int* __restrict__ sp) {
    int n = blockIdx.x * 256 + threadIdx.x;
    if (n >= HDIM) return;
    const int t = read_t(tp);
    const float sf = read_s(sp);

    g_gate2[n] = sigmoidf_(sf * efc2[(size_t)t * HDIM + n]);
    if (n >= ADIM) return;
    g_gate1[n] = sigmoidf_(sf * efc1[(size_t)t * ADIM + n]);

    float acc[10];
#pragma unroll
    for (int j = 0; j < 10; j++) acc[j] = 0.0f;
    for (int k = 0; k < HDIM; k++) {
        float gl = sigmoidf_(sf * elarger[(size_t)t * HDIM + k]);
        float gw = gl * fc1_w[(size_t)k * ADIM + n];
#pragma unroll
        for (int j = 0; j < 9; j++) acc[j] += gw * larger_w[j * HDIM + k];
        acc[9] += gw * larger_b[k];
    }
#pragma unroll
    for (int j = 0; j < 9; j++) g_w9[j * ADIM + n] = acc[j];
    g_w9[9 * ADIM + n] = acc[9] + fc1_b[n];
}

// ---------------------------------------------------------------------------
// Fused sem GEMM (x @ W30, 128x32 tile, K=768, cp.async 2-stage) + capsule
// dynamic routing in the epilogue. Writes g_vote in (K,BS,C) layout.
// ---------------------------------------------------------------------------
__global__ __launch_bounds__(256) void semroute_kernel(const float* __restrict__ x,
                                                       const float* __restrict__ w30,
                                                       const float* __restrict__ route_w,
                                                       const int* __restrict__ tp, int M) {
    constexpr int BM = 128, BK = 32, AST = BK + 4, BST = 40;
    __shared__ float As[2 * BM * AST];
    __shared__ float Bs[2 * BK * BST];

    const int tid = threadIdx.x;
    const int wid = tid >> 5, lane = tid & 31;
    const int gr = lane >> 2, gc = lane & 3;
    const int wm = wid * 16;            // 8 warps x 16 rows
    const int m0 = blockIdx.x * BM;

    float acc[4][4];
#pragma unroll
    for (int j = 0; j < 4; j++)
#pragma unroll
        for (int q = 0; q < 4; q++) acc[j][q] = 0.0f;

    const int NC = HDIM / BK;  // 24

    {
        const float* ab = x + (size_t)m0 * HDIM;
#pragma unroll
        for (int it = 0; it < 4; it++) {
            int idx = tid + it * 256;
            int r = idx >> 3, c4 = (idx & 7) << 2;
            CP16(As + r * AST + c4, ab + (size_t)r * HDIM + c4);
        }
        int r = tid >> 3, c4 = (tid & 7) << 2;
        CP16(Bs + r * BST + c4, w30 + r * 32 + c4);
        CP_COMMIT();
    }

    for (int kc = 0; kc < NC; kc++) {
        int st = kc & 1;
        if (kc + 1 < NC) {
            const float* ab = x + (size_t)m0 * HDIM + (kc + 1) * BK;
            float* ad = As + (st ^ 1) * BM * AST;
#pragma unroll
            for (int it = 0; it < 4; it++) {
                int idx = tid + it * 256;
                int r = idx >> 3, c4 = (idx & 7) << 2;
                CP16(ad + r * AST + c4, ab + (size_t)r * HDIM + c4);
            }
            float* bd = Bs + (st ^ 1) * BK * BST;
            int r = tid >> 3, c4 = (tid & 7) << 2;
            CP16(bd + r * BST + c4, w30 + (size_t)(kc + 1) * BK * 32 + r * 32 + c4);
            CP_COMMIT();
            CP_WAIT1();
        } else {
            CP_WAIT0();
        }
        __syncthreads();

        const float* Al = As + st * BM * AST;
        const float* Bl = Bs + st * BK * BST;
#pragma unroll
        for (int kk = 0; kk < BK; kk += 8) {
            uint32_t a_[4], b_[4][2];
            int row = wm + gr;
            a_[0] = __float_as_uint(Al[row * AST + kk + gc]);
            a_[1] = __float_as_uint(Al[(row + 8) * AST + kk + gc]);
            a_[2] = __float_as_uint(Al[row * AST + kk + gc + 4]);
            a_[3] = __float_as_uint(Al[(row + 8) * AST + kk + gc + 4]);
#pragma unroll
            for (int j = 0; j < 4; j++) {
                int col = j * 8 + gr;
                b_[j][0] = __float_as_uint(Bl[(kk + gc) * BST + col]);
                b_[j][1] = __float_as_uint(Bl[(kk + gc + 4) * BST + col]);
            }
#pragma unroll
            for (int j = 0; j < 4; j++) mma_tf32(acc[j], a_, b_[j]);
        }
        __syncthreads();
    }

    float* sem_s = As;  // reuse: 128 rows, stride 33
    float* rw = Bs;     // reuse: 270 floats
#pragma unroll
    for (int j = 0; j < 4; j++)
#pragma unroll
        for (int q = 0; q < 4; q++) {
            int row = wm + gr + ((q >= 2) ? 8 : 0);
            int col = j * 8 + gc * 2 + (q & 1);
            sem_s[row * 33 + col] = acc[j][q] + __ldg(&g_semb[col]);
        }
    for (int i = tid; i < KCAP * NTASK * CCAP * CCAP; i += 256) rw[i] = route_w[i];
    __syncthreads();

    if (tid < BM) {
        const int m = m0 + tid;
        const int tval = read_t(tp);

        float uf[30];
#pragma unroll
        for (int i = 0; i < 30; i++) uf[i] = sem_s[tid * 33 + i];
#pragma unroll
        for (int c = 0; c < CCAP; c++) {
            float sn = 1e-16f;
#pragma unroll
            for (int n = 0; n < NTASK; n++) {
                float v = uf[c * NTASK + n];
                sn += v * v;
            }
            float sc = sqrtf(sn) / (1.0f + sn);
#pragma unroll
            for (int n = 0; n < NTASK; n++) uf[c * NTASK + n] *= sc;
        }

        for (int k = 0; k < KCAP; k++) {
            float pr[NTASK][CCAP];
#pragma unroll
            for (int n = 0; n < NTASK; n++)
#pragma unroll
                for (int d = 0; d < CCAP; d++) {
                    float s = 0.0f;
#pragma unroll
                    for (int c = 0; c < CCAP; c++)
                        s += uf[n * CCAP + c] * rw[((k * NTASK + n) * CCAP + c) * CCAP + d];
                    pr[n][d] = s;
                }

            float lg[NTASK];
#pragma unroll
            for (int n = 0; n < NTASK; n++) lg[n] = 0.0f;
            float vote[CCAP] = {0.0f, 0.0f, 0.0f};

#pragma unroll
            for (int it = 0; it < 3; it++) {
                float ml[NTASK], mx = -1e30f;
#pragma unroll
                for (int n = 0; n < NTASK; n++) {
                    ml[n] = (n <= tval) ? lg[n] : -10000.0f;
                    mx = fmaxf(mx, ml[n]);
                }
                float p[NTASK], sum = 0.0f;
#pragma unroll
                for (int n = 0; n < NTASK; n++) {
                    p[n] = expf(ml[n] - mx);
                    sum += p[n];
                }
                float inv = 1.0f / sum;
#pragma unroll
                for (int c = 0; c < CCAP; c++) {
                    float s = 0.0f;
#pragma unroll
                    for (int n = 0; n < NTASK; n++) s += p[n] * pr[n][c];
                    vote[c] = s * inv;
                }
                if (it < 2) {
                    float sn = 1e-16f;
#pragma unroll
                    for (int c = 0; c < CCAP; c++) sn += vote[c] * vote[c];
                    float sc = sqrtf(sn) / (1.0f + sn);
#pragma unroll
                    for (int n = 0; n < NTASK; n++) {
                        float s = 0.0f;
#pragma unroll
                        for (int c = 0; c < CCAP; c++) s += pr[n][c] * vote[c];
                        lg[n] += s * sc;
                    }
                }
            }
            float* vp = g_vote + ((size_t)k * M + m) * CCAP;
#pragma unroll
            for (int c = 0; c < CCAP; c++) vp[c] = vote[c];
        }
    }
}

// ---------------------------------------------------------------------------
// Big pipelined TF32 GEMM, 128x128x16 tiles, 2-stage cp.async.
// Static smem 37,888 B; __launch_bounds__(256,2) => 2 CTAs/SM (128 regs).
// Epilogue operands are staged AFTER the mainloop into the As buffer
// (free post-loop) to keep mainloop register pressure low.
// EPI 1 (fc1): a1 = gelu(x@W1 + h9@W9 + W9row9) * gate1
// EPI 2 (fc2): out = x + gelu(a1@W2 + b2) * gate2
// ---------------------------------------------------------------------------
template <int EPI>
__global__ __launch_bounds__(256, 2) void gemm_big(const float* __restrict__ A,
                                                   const float* __restrict__ Bm,
                                                   float* __restrict__ C, int M, int N, int K,
                                                   const float* __restrict__ bias,
                                                   const float* __restrict__ gate,
                                                   const float* __restrict__ xres,
                                                   const float* __restrict__ w9,
                                                   const float* __restrict__ h9g) {
    constexpr int BM = 128, BN = 128, BK = 16;
    constexpr int AST = BK + 4, BST = BN + 8;
    __shared__ float As[2 * BM * AST];   // 20480 B (reused for epilogue staging)
    __shared__ float Bs[2 * BK * BST];   // 17408 B

    const int tid = threadIdx.x;
    const int wid = tid >> 5, lane = tid & 31;
    const int gr = lane >> 2, gc = lane & 3;
    const int wm = (wid >> 2) * 64;       // 2 warp-rows
    const int wn = (wid & 3) * 32;        // 4 warp-cols
    const int m0 = blockIdx.y * BM, n0 = blockIdx.x * BN;

    float acc[4][4][4];
#pragma unroll
    for (int i = 0; i < 4; i++)
#pragma unroll
        for (int j = 0; j < 4; j++)
#pragma unroll
            for (int q = 0; q < 4; q++) acc[i][j][q] = 0.0f;

    const int NC = K / BK;

    // prefetch chunk 0: A 128x16 = 512 float4, B 16x128 = 512 float4
    {
        const float* ab = A + (size_t)m0 * K;
#pragma unroll
        for (int it = 0; it < 2; it++) {
            int idx = tid + it * 256;
            int r = idx >> 2, c4 = (idx & 3) << 2;
            CP16(As + r * AST + c4, ab + (size_t)r * K + c4);
        }
        const float* bb = Bm + n0;
#pragma unroll
        for (int it = 0; it < 2; it++) {
            int idx = tid + it * 256;
            int r = idx >> 5, c4 = (idx & 31) << 2;
            CP16(Bs + r * BST + c4, bb + (size_t)r * N + c4);
        }
        CP_COMMIT();
    }

    for (int kc = 0; kc < NC; kc++) {
        int st = kc & 1;
        if (kc + 1 < NC) {
            const float* ab = A + (size_t)m0 * K + (kc + 1) * BK;
            float* ad = As + (st ^ 1) * BM * AST;
#pragma unroll
            for (int it = 0; it < 2; it++) {
                int idx = tid + it * 256;
                int r = idx >> 2, c4 = (idx & 3) << 2;
                CP16(ad + r * AST + c4, ab + (size_t)r * K + c4);
            }
            const float* bb = Bm + (size_t)(kc + 1) * BK * N + n0;
            float* bd = Bs + (st ^ 1) * BK * BST;
#pragma unroll
            for (int it = 0; it < 2; it++) {
                int idx = tid + it * 256;
                int r = idx >> 5, c4 = (idx & 31) << 2;
                CP16(bd + r * BST + c4, bb + (size_t)r * N + c4);
            }
            CP_COMMIT();
            CP_WAIT1();
        } else {
            CP_WAIT0();
        }
        __syncthreads();

        const float* Al = As + st * BM * AST;
        const float* Bl = Bs + st * BK * BST;
#pragma unroll
        for (int kk = 0; kk < BK; kk += 8) {
            uint32_t a_[4][4], b_[4][2];
#pragma unroll
            for (int i = 0; i < 4; i++) {
                int row = wm + i * 16 + gr;
                a_[i][0] = __float_as_uint(Al[row * AST + kk + gc]);
                a_[i][1] = __float_as_uint(Al[(row + 8) * AST + kk + gc]);
                a_[i][2] = __float_as_uint(Al[row * AST + kk + gc + 4]);
                a_[i][3] = __float_as_uint(Al[(row + 8) * AST + kk + gc + 4]);
            }
#pragma unroll
            for (int j = 0; j < 4; j++) {
                int col = wn + j * 8 + gr;
                b_[j][0] = __float_as_uint(Bl[(kk + gc) * BST + col]);
                b_[j][1] = __float_as_uint(Bl[(kk + gc + 4) * BST + col]);
            }
#pragma unroll
            for (int i = 0; i < 4; i++)
#pragma unroll
                for (int j = 0; j < 4; j++) mma_tf32(acc[i][j], a_[i], b_[j]);
        }
        __syncthreads();
    }

    // ---- epilogue operand staging into the (now free) As buffer ----
    float* ex = As;
    if (EPI == 1) {
        float* h9s = ex;                  // 1152 floats
        float* w9s = ex + 1152;           // 1280 floats
        float* gs = ex + 2432;            // 128 floats
        const float4* hsrc = (const float4*)(h9g + (size_t)m0 * 9);
        for (int i = tid; i < 288; i += 256) ((float4*)h9s)[i] = hsrc[i];
        for (int i = tid; i < 320; i += 256) {
            int j = i >> 5, c = i & 31;
            ((float4*)w9s)[j * 32 + c] = *(const float4*)(w9 + j * ADIM + n0 + c * 4);
        }
        if (tid < 32) ((float4*)gs)[tid] = *(const float4*)(gate + n0 + tid * 4);
    } else {
        float* biass = ex;                // 128 floats
        float* gs = ex + 128;             // 128 floats
        if (tid < 32)
            ((float4*)biass)[tid] = *(const float4*)(bias + n0 + tid * 4);
        else if (tid < 64)
            ((float4*)gs)[tid - 32] = *(const float4*)(gate + n0 + (tid - 32) * 4);
    }
    __syncthreads();

    const float* h9s = ex;
    const float* w9s = ex + 1152;
    const float* gsE = (EPI == 1) ? (ex + 2432) : (ex + 128);
    const float* biass = ex;

#pragma unroll
    for (int i = 0; i < 4; i++) {
#pragma unroll
        for (int j = 0; j < 4; j++) {
            int rB0 = wm + i * 16 + gr;
            int cB = wn + j * 8 + gc * 2;
            int cG = n0 + cB;
#pragma unroll
            for (int h = 0; h < 2; h++) {
                int rB = rB0 + h * 8;
                int rG = m0 + rB;
                float v0 = acc[i][j][h * 2 + 0];
                float v1 = acc[i][j][h * 2 + 1];
                if (EPI == 1) {
                    float c0 = w9s[9 * BN + cB], c1 = w9s[9 * BN + cB + 1];
                    const float* hr = h9s + rB * 9;
#pragma unroll
                    for (int jj = 0; jj < 9; jj++) {
                        float hv = hr[jj];
                        c0 += hv * w9s[jj * BN + cB];
                        c1 += hv * w9s[jj * BN + cB + 1];
                    }
                    v0 = gelu_exact(v0 + c0) * gsE[cB];
                    v1 = gelu_exact(v1 + c1) * gsE[cB + 1];
                } else {
                    v0 = gelu_exact(v0 + biass[cB]) * gsE[cB];
                    v1 = gelu_exact(v1 + biass[cB + 1]) * gsE[cB + 1];
                    float2 xv = *(const float2*)(xres + (size_t)rG * N + cG);
                    v0 += xv.x;
                    v1 += xv.y;
                }
                *(float2*)(C + (size_t)rG * N + cG) = make_float2(v0, v1);
            }
        }
    }
}

// ---------------------------------------------------------------------------
// Launch — kernel launches only; no attribute calls, no dynamic smem.
// ---------------------------------------------------------------------------
extern "C" void kernel_launch(void* const* d_in, const int* in_sizes, int n_in,
                              void* d_out, int out_size) {
    const float* x        = (const float*)d_in[0];
    const int*   tp       = (const int*)d_in[1];
    const int*   sp       = (const int*)d_in[2];
    const float* fc1_w    = (const float*)d_in[3];
    const float* fc1_b    = (const float*)d_in[4];
    const float* fc2_w    = (const float*)d_in[5];
    const float* fc2_b    = (const float*)d_in[6];
    const float* efc1     = (const float*)d_in[7];
    const float* efc2     = (const float*)d_in[8];
    const float* sem_w    = (const float*)d_in[9];
    const float* sem_b    = (const float*)d_in[10];
    const float* route_w  = (const float*)d_in[11];
    const float* larger_w = (const float*)d_in[12];
    const float* larger_b = (const float*)d_in[13];
    const float* elarger  = (const float*)d_in[14];
    float* out = (float*)d_out;

    const int M = in_sizes[0] / HDIM;  // 32768

    float *p_w30, *p_vote, *p_w9, *p_g1, *p_g2, *p_a1;
    cudaGetSymbolAddress((void**)&p_w30, g_w30);
    cudaGetSymbolAddress((void**)&p_vote, g_vote);
    cudaGetSymbolAddress((void**)&p_w9, g_w9);
    cudaGetSymbolAddress((void**)&p_g1, g_gate1);
    cudaGetSymbolAddress((void**)&p_g2, g_gate2);
    cudaGetSymbolAddress((void**)&p_a1, g_a1);

    // 1) weight reorders + rank-9 correction + gates
    prep_kernel<<<(HDIM * 32 + 32 + 255) / 256, 256>>>(sem_w, sem_b);
    w9_kernel<<<3, 256>>>(larger_w, larger_b, elarger, fc1_w, fc1_b, efc1, efc2, tp, sp);

    // 2) sem GEMM + routing fused
    semroute_kernel<<<M / 128, 256>>>(x, p_w30, route_w, tp, M);

    // 3) fc1: a1 = gelu(x@W1 + rank9) * gate1
    gemm_big<1><<<dim3(ADIM / 128, M / 128), 256>>>(
        x, fc1_w, p_a1, M, ADIM, HDIM, nullptr, p_g1, nullptr, p_w9, p_vote);

    // 4) fc2: out = x + gelu(a1@W2 + b2) * gate2
    gemm_big<2><<<dim3(HDIM / 128, M / 128), 256>>>(
        p_a1, fc2_w, out, M, HDIM, ADIM, fc2_b, p_g2, x, nullptr, nullptr);
}